// round 13
// baseline (speedup 1.0000x reference)
#include <cuda_runtime.h>
#include <cuda_bf16.h>

#define BATCH 2
#define LSEQ 2048
#define HDIM 1024
#define NST 16
#define MROWS (BATCH*LSEQ)     // 4096
#define DT_MIN_V 0.001f
#define DT_MAX_V 0.02f
#define NGRP 32
#define GLEN (LSEQ/NGRP)       // 64 steps per group
#define NCH (BATCH*HDIM)       // 2048
#define LOG2E 1.4426950408889634f

typedef unsigned long long u64;

// Scratch (__device__ globals: allocation-free rule)
__device__ float g_dtv[BATCH*LSEQ*HDIM];       // (B,L,H) clamped dt (fp32)
__device__ __nv_bfloat16 g_Ub[MROWS*HDIM];     // bf16 copy of u (GEMM A)
__device__ __nv_bfloat16 g_Wb[HDIM*HDIM];      // bf16 copy of W_dt (GEMM B)
// group-level aggregates / start states, layout [group][n][s]
__device__ float  g_Pg [NGRP*NST*NCH];
__device__ float  g_Sg [NGRP*NST*NCH];
__device__ float  g_Xg [NGRP*NST*NCH];
// Per-channel constant tables, packed pairs, layout [pair i][h]
__device__ u64 g_am2T[8*HDIM];
__device__ u64 g_al2T[8*HDIM];
__device__ u64 g_c2T [8*HDIM];

__device__ __forceinline__ u64 ffma2(u64 a, u64 b, u64 c){
    u64 d;
    asm("fma.rn.f32x2 %0, %1, %2, %3;" : "=l"(d) : "l"(a), "l"(b), "l"(c));
    return d;
}
__device__ __forceinline__ u64 f2u(float x, float y){
    u64 v; asm("mov.b64 %0, {%1, %2};" : "=l"(v) : "f"(x), "f"(y)); return v;
}
__device__ __forceinline__ float2 u2f(u64 v){
    float2 r; asm("mov.b64 {%0, %1}, %2;" : "=f"(r.x), "=f"(r.y) : "l"(v)); return r;
}

// ---------------------------------------------------------------------------
// Convert U and W to bf16 (runs once per launch).
// ---------------------------------------------------------------------------
__global__ void convert_bf16_kernel(const float* __restrict__ U,
                                    const float* __restrict__ W){
    const int NU = MROWS * HDIM / 4;
    int i = blockIdx.x * blockDim.x + threadIdx.x;
    if (i < NU){
        const float4 v = __ldg((const float4*)U + i);
        __nv_bfloat162 lo = __floats2bfloat162_rn(v.x, v.y);
        __nv_bfloat162 hi = __floats2bfloat162_rn(v.z, v.w);
        ((uint2*)g_Ub)[i] = make_uint2(*(unsigned*)&lo, *(unsigned*)&hi);
    } else {
        i -= NU;
        const float4 v = __ldg((const float4*)W + i);
        __nv_bfloat162 lo = __floats2bfloat162_rn(v.x, v.y);
        __nv_bfloat162 hi = __floats2bfloat162_rn(v.z, v.w);
        ((uint2*)g_Wb)[i] = make_uint2(*(unsigned*)&lo, *(unsigned*)&hi);
    }
}

// ---------------------------------------------------------------------------
// Precompute per-channel constants (runs once).
// ---------------------------------------------------------------------------
__global__ void precompute_kernel(const float* __restrict__ Alog,
                                  const float* __restrict__ Bp,
                                  const float* __restrict__ Cp){
    const int h = blockIdx.x * blockDim.x + threadIdx.x;
    float am[NST], al2[NST], cs[NST];
    #pragma unroll
    for (int n = 0; n < NST; n++){
        const float A = -expf(Alog[h * NST + n]);
        al2[n] = A * LOG2E;
        am[n]  = exp2f(0.02f * al2[n]);
        cs[n]  = Cp[h * NST + n] * (am[n] - 1.f) * Bp[h * NST + n] / A;
    }
    #pragma unroll
    for (int i = 0; i < 8; i++){
        g_am2T[i * HDIM + h] = f2u(am[2 * i],  am[2 * i + 1]);
        g_al2T[i * HDIM + h] = f2u(al2[2 * i], al2[2 * i + 1]);
        g_c2T [i * HDIM + h] = f2u(cs[2 * i],  cs[2 * i + 1]);
    }
}

// ---------------------------------------------------------------------------
// BF16 tensor-core GEMM: 128x256 block tile (128 blocks = one wave), BK=64,
// 16 kt, mma.m16n8k16.bf16, fp32 accum. Epilogue -> g_dtv (fp32).
// ---------------------------------------------------------------------------
__device__ __forceinline__ void cp16(float* s, const void* g){
    unsigned sa = (unsigned)__cvta_generic_to_shared(s);
    asm volatile("cp.async.cg.shared.global [%0], [%1], 16;" :: "r"(sa), "l"(g));
}
__device__ __forceinline__ void ldsm4(unsigned* r, unsigned addr){
    asm volatile("ldmatrix.sync.aligned.m8n8.x4.shared.b16 {%0,%1,%2,%3}, [%4];"
        : "=r"(r[0]), "=r"(r[1]), "=r"(r[2]), "=r"(r[3]) : "r"(addr));
}
__device__ __forceinline__ void mma_bf16(float* d, const unsigned* a,
                                         unsigned b0, unsigned b1){
    asm volatile(
        "mma.sync.aligned.m16n8k16.row.col.f32.bf16.bf16.f32 "
        "{%0,%1,%2,%3}, {%4,%5,%6,%7}, {%8,%9}, {%0,%1,%2,%3};"
        : "+f"(d[0]), "+f"(d[1]), "+f"(d[2]), "+f"(d[3])
        : "r"(a[0]), "r"(a[1]), "r"(a[2]), "r"(a[3]), "r"(b0), "r"(b1));
}

#define GEMM_SMEM_STG 12288
#define GEMM_B_OFF    4096

__global__ __launch_bounds__(256, 1) void gemm_bf16_kernel(
        const float* __restrict__ bias){
    extern __shared__ float smem[];
    const int tid  = threadIdx.x;
    const int lane = tid & 31;
    const int wid  = tid >> 5;
    const int wm   = wid & 1;
    const int wn   = wid >> 1;
    const int bm   = blockIdx.y * 128;
    const int bn   = blockIdx.x * 256;

    float acc[4][8][4];
    #pragma unroll
    for (int i = 0; i < 4; i++)
        #pragma unroll
        for (int j = 0; j < 8; j++)
            #pragma unroll
            for (int r = 0; r < 4; r++) acc[i][j][r] = 0.f;

    const int lrow = tid >> 3;
    const int lkc  = tid & 7;

    unsigned smemBase = (unsigned)__cvta_generic_to_shared(smem);
    const unsigned aRowOff = (unsigned)((wm * 64 + (lane & 15)) * 128);
    const unsigned bRowOff = (unsigned)((wn * 64 + ((lane & 16) >> 1) + (lane & 7)) * 128);
    int physA[4], physB[4];
    #pragma unroll
    for (int ks = 0; ks < 4; ks++){
        physA[ks] = ((2 * ks + (lane >> 4)) ^ (lane & 7)) * 16;
        physB[ks] = ((2 * ks + ((lane >> 3) & 1)) ^ (lane & 7)) * 16;
    }

    #define LOAD_TILE(KT, STG) do {                                            \
        float* A_s = smem + (STG) * GEMM_SMEM_STG;                             \
        float* B_s = A_s + GEMM_B_OFF;                                         \
        _Pragma("unroll")                                                      \
        for (int i = 0; i < 4; i++){                                           \
            int row  = lrow + i * 32;                                          \
            int phys = lkc ^ (row & 7);                                        \
            cp16(A_s + row * 32 + phys * 4,                                    \
                 (const char*)g_Ub + (size_t)(bm + row) * 2048 + (KT) * 128 + lkc * 16); \
        }                                                                      \
        _Pragma("unroll")                                                      \
        for (int i = 0; i < 8; i++){                                           \
            int row  = lrow + i * 32;                                          \
            int phys = lkc ^ (row & 7);                                        \
            cp16(B_s + row * 32 + phys * 4,                                    \
                 (const char*)g_Wb + (size_t)(bn + row) * 2048 + (KT) * 128 + lkc * 16); \
        }                                                                      \
        asm volatile("cp.async.commit_group;");                                \
    } while (0)

    LOAD_TILE(0, 0);

    for (int kt = 0; kt < 16; kt++){
        const int cur = kt & 1;
        if (kt < 15) LOAD_TILE(kt + 1, cur ^ 1);
        if (kt < 15) asm volatile("cp.async.wait_group 1;");
        else         asm volatile("cp.async.wait_group 0;");
        __syncthreads();

        unsigned aB = smemBase + cur * (GEMM_SMEM_STG * 4) + aRowOff;
        unsigned bB = smemBase + cur * (GEMM_SMEM_STG * 4) + GEMM_B_OFF * 4 + bRowOff;
        #pragma unroll
        for (int ks = 0; ks < 4; ks++){
            unsigned a[4][4], bb[4][4];
            #pragma unroll
            for (int mt = 0; mt < 4; mt++)
                ldsm4(a[mt], aB + mt * 16 * 128 + physA[ks]);
            #pragma unroll
            for (int tp = 0; tp < 4; tp++)
                ldsm4(bb[tp], bB + tp * 16 * 128 + physB[ks]);
            #pragma unroll
            for (int mt = 0; mt < 4; mt++)
                #pragma unroll
                for (int nt = 0; nt < 8; nt++)
                    mma_bf16(acc[mt][nt], a[mt],
                             bb[nt >> 1][(nt & 1) * 2], bb[nt >> 1][(nt & 1) * 2 + 1]);
        }
        __syncthreads();
    }

    const int rbase = bm + wm * 64 + (lane >> 2);
    const int gbase = bn + wn * 64 + 2 * (lane & 3);
    float bv[8][2];
    #pragma unroll
    for (int nt = 0; nt < 8; nt++){
        bv[nt][0] = __ldg(bias + gbase + nt * 8);
        bv[nt][1] = __ldg(bias + gbase + nt * 8 + 1);
    }
    #pragma unroll
    for (int mt = 0; mt < 4; mt++)
        #pragma unroll
        for (int nt = 0; nt < 8; nt++)
            #pragma unroll
            for (int rr = 0; rr < 2; rr++){
                const int m = rbase + mt * 16 + rr * 8;
                const int g0 = gbase + nt * 8;
                float v0 = acc[mt][nt][rr * 2]     + bv[nt][0];
                float v1 = acc[mt][nt][rr * 2 + 1] + bv[nt][1];
                float2 o;
                o.x = fminf(fmaxf(__expf(v0), DT_MIN_V), DT_MAX_V);
                o.y = fminf(fmaxf(__expf(v1), DT_MIN_V), DT_MAX_V);
                *(float2*)&g_dtv[(size_t)m * HDIM + g0] = o;
            }
}

// ---------------------------------------------------------------------------
// Step macros (register-only, fully inline).
// ---------------------------------------------------------------------------
#define FAST_STEP(uu) do {                                                     \
    const u64 _u2 = f2u((uu), (uu));                                           \
    _Pragma("unroll")                                                          \
    for (int _i = 0; _i < 8; _i++) x2[_i] = ffma2(x2[_i], am2[_i], _u2);       \
} while (0)

#define SLOW_STEP(dtv, uv) do {                                                \
    _Pragma("unroll")                                                          \
    for (int _i = 0; _i < 8; _i++){                                            \
        float2 _xv = u2f(x2[_i]);                                              \
        const float2 _av = u2f(g_am2T[_i * HDIM + h]);                         \
        const float2 _lv = u2f(g_al2T[_i * HDIM + h]);                         \
        {                                                                      \
            const float _ab = exp2f((dtv) * _lv.x);                            \
            _xv.x = fmaf(_xv.x, _ab, (_ab - 1.f) / (_av.x - 1.f) * (uv));      \
        }                                                                      \
        {                                                                      \
            const float _ab = exp2f((dtv) * _lv.y);                            \
            _xv.y = fmaf(_xv.y, _ab, (_ab - 1.f) / (_av.y - 1.f) * (uv));      \
        }                                                                      \
        x2[_i] = f2u(_xv.x, _xv.y);                                            \
    }                                                                          \
} while (0)

// ---------------------------------------------------------------------------
// Pass 1: per-(channel, group) reduce over 64 steps -> (Pg, Sg).
// Software-pipelined: 4 batches of 16; next batch's loads issued before the
// current batch's compute (double-buffered register arrays).
// ---------------------------------------------------------------------------
__global__ __launch_bounds__(128) void scan_reduce_kernel(const float* __restrict__ u){
    const int tid = threadIdx.x;
    const int s = blockIdx.x * 128 + tid;
    const int g = blockIdx.y;
    const int b = s >> 10;
    const int h = s & 1023;

    u64 am2[8], x2[8];
    #pragma unroll
    for (int i = 0; i < 8; i++){
        am2[i] = g_am2T[i * HDIM + h];
        x2[i] = 0ull;
    }

    const size_t base = ((size_t)(b * LSEQ + g * GLEN)) * HDIM + h;
    const float* up = u + base;
    const float* dp = g_dtv + base;
    float dtsum = 0.f;

    #define RLOAD(UU, DV, BT) do {                                             \
        _Pragma("unroll")                                                      \
        for (int _j = 0; _j < 16; _j++){                                       \
            UU[_j] = __ldg(up + (size_t)((BT) * 16 + _j) * HDIM);              \
            DV[_j] = __ldg(dp + (size_t)((BT) * 16 + _j) * HDIM);              \
        }                                                                      \
    } while (0)

    #define RPROC(UU, DV) do {                                                 \
        bool _fast = true;                                                     \
        _Pragma("unroll")                                                      \
        for (int _j = 0; _j < 16; _j++){ _fast &= (DV[_j] == DT_MAX_V); dtsum += DV[_j]; } \
        if (_fast){                                                            \
            _Pragma("unroll")                                                  \
            for (int _j = 0; _j < 16; _j++) FAST_STEP(UU[_j]);                 \
        } else {                                                               \
            _Pragma("unroll")                                                  \
            for (int _j = 0; _j < 16; _j++){                                   \
                if (DV[_j] == DT_MAX_V) FAST_STEP(UU[_j]);                     \
                else                    SLOW_STEP(DV[_j], UU[_j]);             \
            }                                                                  \
        }                                                                      \
    } while (0)

    {
        float uuA[16], dvA[16], uuB[16], dvB[16];
        RLOAD(uuA, dvA, 0);
        RLOAD(uuB, dvB, 1);
        RPROC(uuA, dvA);
        RLOAD(uuA, dvA, 2);
        RPROC(uuB, dvB);
        RLOAD(uuB, dvB, 3);
        RPROC(uuA, dvA);
        RPROC(uuB, dvB);
    }
    #undef RLOAD
    #undef RPROC

    float* Pp = g_Pg + (size_t)g * NST * NCH + s;
    float* Sp = g_Sg + (size_t)g * NST * NCH + s;
    #pragma unroll
    for (int i = 0; i < 8; i++){
        const float2 lv = u2f(g_al2T[i * HDIM + h]);
        const float2 xv = u2f(x2[i]);
        Pp[(size_t)(2 * i)     * NCH] = exp2f(lv.x * dtsum);
        Pp[(size_t)(2 * i + 1) * NCH] = exp2f(lv.y * dtsum);
        Sp[(size_t)(2 * i)     * NCH] = xv.x;
        Sp[(size_t)(2 * i + 1) * NCH] = xv.y;
    }
}

// ---------------------------------------------------------------------------
// Pass 2: fold 32 group aggregates -> group start states Xg.
// ---------------------------------------------------------------------------
#define STRIDE4 (NST*NCH/4)
__global__ void scan_stitch_kernel(){
    const int id = blockIdx.x * blockDim.x + threadIdx.x;  // 0..8191
    const float4* Pg4 = (const float4*)g_Pg;
    const float4* Sg4 = (const float4*)g_Sg;
    float4* Xg4 = (float4*)g_Xg;
    float4 x = make_float4(0.f, 0.f, 0.f, 0.f);
    #pragma unroll 1
    for (int r = 0; r < NGRP / 8; r++){
        float4 Pg[8], Sg[8];
        #pragma unroll
        for (int c = 0; c < 8; c++){
            Pg[c] = Pg4[(size_t)(r * 8 + c) * STRIDE4 + id];
            Sg[c] = Sg4[(size_t)(r * 8 + c) * STRIDE4 + id];
        }
        #pragma unroll
        for (int c = 0; c < 8; c++){
            Xg4[(size_t)(r * 8 + c) * STRIDE4 + id] = x;
            x.x = fmaf(Pg[c].x, x.x, Sg[c].x);
            x.y = fmaf(Pg[c].y, x.y, Sg[c].y);
            x.z = fmaf(Pg[c].z, x.z, Sg[c].z);
            x.w = fmaf(Pg[c].w, x.w, Sg[c].w);
        }
    }
}

// ---------------------------------------------------------------------------
// Pass 3: final scan + output. Software-pipelined 8 batches of 8 steps.
// ---------------------------------------------------------------------------
__global__ __launch_bounds__(128) void scan_final_kernel(
        const float* __restrict__ Dp, const float* __restrict__ u,
        float* __restrict__ out){
    const int tid = threadIdx.x;
    const int s = blockIdx.x * 128 + tid;
    const int g = blockIdx.y;
    const int b = s >> 10;
    const int h = s & 1023;

    u64 am2[8], c2[8], x2[8];
    #pragma unroll
    for (int i = 0; i < 8; i++){
        am2[i] = g_am2T[i * HDIM + h];
        c2[i]  = g_c2T [i * HDIM + h];
    }
    const float Dh = __ldg(Dp + h);

    {
        const float* Xp = g_Xg + (size_t)g * NST * NCH + s;
        #pragma unroll
        for (int i = 0; i < 8; i++)
            x2[i] = f2u(Xp[(size_t)(2 * i) * NCH], Xp[(size_t)(2 * i + 1) * NCH]);
    }

    const size_t base = ((size_t)(b * LSEQ + g * GLEN)) * HDIM + h;
    const float* up = u + base;
    const float* dp = g_dtv + base;
    float* op = out + base;

    #define Y_EMIT(j, uv) do {                                                 \
        u64 ya = 0ull, yb = 0ull;                                              \
        _Pragma("unroll")                                                      \
        for (int _i = 0; _i < 4; _i++) ya = ffma2(c2[_i], x2[_i], ya);         \
        _Pragma("unroll")                                                      \
        for (int _i = 4; _i < 8; _i++) yb = ffma2(c2[_i], x2[_i], yb);         \
        const float2 _va = u2f(ya);                                            \
        const float2 _vb = u2f(yb);                                            \
        op[(size_t)(j) * HDIM] = fmaf(Dh, (uv), (_va.x + _va.y) + (_vb.x + _vb.y)); \
    } while (0)

    #define FLOAD(UU, DV, BT) do {                                             \
        _Pragma("unroll")                                                      \
        for (int _j = 0; _j < 8; _j++){                                        \
            UU[_j] = __ldg(up + (size_t)((BT) * 8 + _j) * HDIM);               \
            DV[_j] = __ldg(dp + (size_t)((BT) * 8 + _j) * HDIM);               \
        }                                                                      \
    } while (0)

    #define FPROC(UU, DV, BT) do {                                             \
        bool _fast = true;                                                     \
        _Pragma("unroll")                                                      \
        for (int _j = 0; _j < 8; _j++) _fast &= (DV[_j] == DT_MAX_V);          \
        if (_fast){                                                            \
            _Pragma("unroll")                                                  \
            for (int _j = 0; _j < 8; _j++){                                    \
                FAST_STEP(UU[_j]);                                             \
                Y_EMIT((BT) * 8 + _j, UU[_j]);                                 \
            }                                                                  \
        } else {                                                               \
            _Pragma("unroll")                                                  \
            for (int _j = 0; _j < 8; _j++){                                    \
                if (DV[_j] == DT_MAX_V) FAST_STEP(UU[_j]);                     \
                else                    SLOW_STEP(DV[_j], UU[_j]);             \
                Y_EMIT((BT) * 8 + _j, UU[_j]);                                 \
            }                                                                  \
        }                                                                      \
    } while (0)

    {
        float uuA[8], dvA[8], uuB[8], dvB[8];
        FLOAD(uuA, dvA, 0);
        FLOAD(uuB, dvB, 1);
        FPROC(uuA, dvA, 0);
        FLOAD(uuA, dvA, 2);
        FPROC(uuB, dvB, 1);
        FLOAD(uuB, dvB, 3);
        FPROC(uuA, dvA, 2);
        FLOAD(uuA, dvA, 4);
        FPROC(uuB, dvB, 3);
        FLOAD(uuB, dvB, 5);
        FPROC(uuA, dvA, 4);
        FLOAD(uuA, dvA, 6);
        FPROC(uuB, dvB, 5);
        FLOAD(uuB, dvB, 7);
        FPROC(uuA, dvA, 6);
        FPROC(uuB, dvB, 7);
    }
    #undef FLOAD
    #undef FPROC
    #undef Y_EMIT
}

// ---------------------------------------------------------------------------
extern "C" void kernel_launch(void* const* d_in, const int* in_sizes, int n_in,
                              void* d_out, int out_size){
    const float* u    = (const float*)d_in[0];
    const float* Alog = (const float*)d_in[1];
    const float* Bp   = (const float*)d_in[2];
    const float* Cp   = (const float*)d_in[3];
    const float* Dp   = (const float*)d_in[4];
    const float* Wdt  = (const float*)d_in[5];
    const float* bdt  = (const float*)d_in[6];
    float* out = (float*)d_out;

    cudaFuncSetAttribute(gemm_bf16_kernel,
                         cudaFuncAttributeMaxDynamicSharedMemorySize, 98304);

    convert_bf16_kernel<<<(MROWS * HDIM / 4 + HDIM * HDIM / 4) / 256, 256>>>(u, Wdt);
    precompute_kernel<<<HDIM / 128, 128>>>(Alog, Bp, Cp);

    dim3 ggrid(HDIM / 256, MROWS / 128);            // (4, 32) = 128 blocks
    gemm_bf16_kernel<<<ggrid, 256, 98304>>>(bdt);

    scan_reduce_kernel<<<dim3(NCH / 128, NGRP), 128>>>(u);
    scan_stitch_kernel<<<STRIDE4 / 256, 256>>>();
    scan_final_kernel<<<dim3(NCH / 128, NGRP), 128>>>(Dp, u, out);
}